// round 9
// baseline (speedup 1.0000x reference)
#include <cuda_runtime.h>
#include <cuda_fp16.h>
#include <cstdint>

// Problem shapes (fixed by the dataset)
#define T_DIM 2048
#define H_DIM 1024
#define E_DIM 8
#define FFN_DIM 1408
#define FFN2_DIM 2816
#define NPAIR 4096
#define NPAD (NPAIR + 128)

// ---------------- scratch (device globals) ----------------------------------
__device__ int   g_topk_idx[T_DIM * 2];
__device__ float g_topk_w[T_DIM * 2];
__device__ int   g_tok[NPAIR];
__device__ int   g_slot[T_DIM * 2];
__device__ int   g_base[E_DIM];
__device__ int   g_cnt[E_DIM];
__device__ __align__(16) __half g_xh[(size_t)NPAD * H_DIM];
__device__ __align__(16) __half g_acth[(size_t)NPAD * FFN_DIM];
__device__ __align__(16) float  g_y[(size_t)NPAIR * H_DIM];
__device__ __align__(16) __half g_w1h[(size_t)E_DIM * H_DIM * FFN2_DIM];   // native [k][n]
__device__ __align__(16) __half g_w2h[(size_t)E_DIM * FFN_DIM * H_DIM];    // native [k][n]

// ---------------- helpers ----------------------------------------------------
__device__ __forceinline__ uint32_t smem_u32(const void* p) {
    uint32_t a;
    asm("{ .reg .u64 t; cvta.to.shared.u64 t, %1; cvt.u32.u64 %0, t; }"
        : "=r"(a) : "l"(p));
    return a;
}
__device__ __forceinline__ void cpa16(uint32_t dst, const void* src) {
    asm volatile("cp.async.cg.shared.global [%0], [%1], 16;" :: "r"(dst), "l"(src));
}
#define CPCOMMIT() asm volatile("cp.async.commit_group;" ::: "memory")
#define CPWAIT2()  asm volatile("cp.async.wait_group 2;" ::: "memory")

__device__ __forceinline__ void ldm4(uint32_t* f, uint32_t a) {
    asm volatile("ldmatrix.sync.aligned.m8n8.x4.shared.b16 {%0,%1,%2,%3}, [%4];"
                 : "=r"(f[0]), "=r"(f[1]), "=r"(f[2]), "=r"(f[3]) : "r"(a));
}
__device__ __forceinline__ void ldm4t(uint32_t* f, uint32_t a) {
    asm volatile("ldmatrix.sync.aligned.m8n8.x4.trans.shared.b16 {%0,%1,%2,%3}, [%4];"
                 : "=r"(f[0]), "=r"(f[1]), "=r"(f[2]), "=r"(f[3]) : "r"(a));
}
__device__ __forceinline__ void mma16(float* c, const uint32_t* a,
                                      uint32_t b0, uint32_t b1) {
    asm volatile(
        "mma.sync.aligned.m16n8k16.row.col.f32.f16.f16.f32 "
        "{%0,%1,%2,%3}, {%4,%5,%6,%7}, {%8,%9}, {%0,%1,%2,%3};"
        : "+f"(c[0]), "+f"(c[1]), "+f"(c[2]), "+f"(c[3])
        : "r"(a[0]), "r"(a[1]), "r"(a[2]), "r"(a[3]), "r"(b0), "r"(b1));
}

// stage: A [128 m][64 k] half = 16KB at +0 ; B [64 k][256 n] half = 32KB at +16384
#define STAGE_BYTES 49152u
#define NSTAGE 4
#define SMEM_BYTES (NSTAGE * STAGE_BYTES)   // 196608

// ---------------- gate: softmax(x @ gate_w^T), top-2, renormalize ----------
__global__ void __launch_bounds__(256) gate_kernel(
    const float* __restrict__ x, const float* __restrict__ gw)
{
    int t = blockIdx.x;
    const float* xr = x + (size_t)t * H_DIM;
    int wid = threadIdx.x >> 5, lane = threadIdx.x & 31;
    __shared__ float sc[E_DIM];

    const float* g = gw + (size_t)wid * H_DIM;
    float s = 0.f;
    for (int i = lane; i < H_DIM; i += 32) s += xr[i] * g[i];
#pragma unroll
    for (int o = 16; o; o >>= 1) s += __shfl_xor_sync(0xffffffffu, s, o);
    if (lane == 0) sc[wid] = s;
    __syncthreads();

    if (threadIdx.x == 0) {
        float m = -1e30f;
#pragma unroll
        for (int e = 0; e < E_DIM; e++) m = fmaxf(m, sc[e]);
        float p[E_DIM], den = 0.f;
#pragma unroll
        for (int e = 0; e < E_DIM; e++) { p[e] = __expf(sc[e] - m); den += p[e]; }
        int i0 = 0;
#pragma unroll
        for (int e = 1; e < E_DIM; e++) if (p[e] > p[i0]) i0 = e;
        int i1 = -1;
#pragma unroll
        for (int e = 0; e < E_DIM; e++)
            if (e != i0 && (i1 < 0 || p[e] > p[i1])) i1 = e;
        float q0 = p[i0] / den, q1 = p[i1] / den;
        float wsum = q0 + q1 + 1e-20f;
        g_topk_idx[2 * t]     = i0;
        g_topk_idx[2 * t + 1] = i1;
        g_topk_w[2 * t]       = q0 / wsum;
        g_topk_w[2 * t + 1]   = q1 / wsum;
    }
}

// ---------------- scatter: deterministic compaction by expert --------------
__global__ void __launch_bounds__(256) scatter_kernel()
{
    int wid = threadIdx.x >> 5, lane = threadIdx.x & 31;
    __shared__ int scnt[E_DIM];

    int c = 0;
    for (int baset = 0; baset < T_DIM; baset += 32) {
        int t = baset + lane;
        bool m = (g_topk_idx[2 * t] == wid) || (g_topk_idx[2 * t + 1] == wid);
        unsigned b = __ballot_sync(0xffffffffu, m);
        c += __popc(b);
    }
    if (lane == 0) scnt[wid] = c;
    __syncthreads();
    if (threadIdx.x == 0) {
        int acc = 0;
        for (int e = 0; e < E_DIM; e++) { g_base[e] = acc; g_cnt[e] = scnt[e]; acc += scnt[e]; }
    }
    __syncthreads();

    int pos = g_base[wid];
    for (int baset = 0; baset < T_DIM; baset += 32) {
        int t = baset + lane;
        int k = -1;
        if (g_topk_idx[2 * t] == wid) k = 0;
        else if (g_topk_idx[2 * t + 1] == wid) k = 1;
        unsigned b = __ballot_sync(0xffffffffu, k >= 0);
        int off = __popc(b & ((1u << lane) - 1u));
        if (k >= 0) {
            g_tok[pos + off] = t;
            g_slot[2 * t + k] = pos + off;
        }
        pos += __popc(b);
    }
}

// ---------------- gather rows -> g_xh (half); 4 rows/block, MLP=4 -----------
__global__ void __launch_bounds__(256) gather_kernel(const float* __restrict__ x)
{
    int p0 = blockIdx.x * 4;
    const float4* src[4];
    float4 v[4];
#pragma unroll
    for (int j = 0; j < 4; j++) {
        int p = p0 + j;
        int t = (p < NPAIR) ? g_tok[p] : 0;
        src[j] = (const float4*)(x + (size_t)t * H_DIM);
    }
#pragma unroll
    for (int j = 0; j < 4; j++) v[j] = src[j][threadIdx.x];
#pragma unroll
    for (int j = 0; j < 4; j++) {
        __half2* d = (__half2*)(g_xh + (size_t)(p0 + j) * H_DIM);
        d[threadIdx.x * 2]     = __floats2half2_rn(v[j].x, v[j].y);
        d[threadIdx.x * 2 + 1] = __floats2half2_rn(v[j].z, v[j].w);
    }
}

// ---------------- streaming f32 -> f16 cast for BOTH weights ----------------
__global__ void __launch_bounds__(256) convW_kernel(
    const float* __restrict__ w1, const float* __restrict__ w2)
{
    const size_t n1 = (size_t)E_DIM * H_DIM * FFN2_DIM / 4;
    const size_t n2 = (size_t)E_DIM * FFN_DIM * H_DIM / 4;
    size_t i = (size_t)blockIdx.x * blockDim.x + threadIdx.x;
    size_t stride = (size_t)gridDim.x * blockDim.x;
    for (; i < n1 + n2; i += stride) {
        const float4* s;
        uint2* d;
        size_t k;
        if (i < n1) { s = (const float4*)w1; d = (uint2*)g_w1h; k = i; }
        else        { s = (const float4*)w2; d = (uint2*)g_w2h; k = i - n1; }
        float4 v = s[k];
        __half2 h0 = __floats2half2_rn(v.x, v.y);
        __half2 h1 = __floats2half2_rn(v.z, v.w);
        d[k] = make_uint2(*(uint32_t*)&h0, *(uint32_t*)&h1);
    }
}

// ---------------- GEMM1: g_xh[128,1024] @ w1h([k][n]) -> swiglu -> g_acth ---
// CTA: 128 M x 128 FFN cols; B stage [64k][256n] (gate cols 0-127, up 128-255).
// 8 warps (2m x 4n), warp tile 64 x 64. Fragment double buffering in-loop.
__global__ void __launch_bounds__(256) gemm1_kernel()
{
    int e = blockIdx.z;
    int cnt = g_cnt[e];
    int m0 = blockIdx.y * 128;
    if (m0 >= cnt) return;
    int base = g_base[e];
    int n0 = blockIdx.x * 128;

    extern __shared__ char smem[];
    uint32_t sb = smem_u32(smem);
    int tid = threadIdx.x, lane = tid & 31, wid = tid >> 5;
    int wm = wid >> 2, wn = wid & 3;

    uint32_t adst[4]; const __half* asrc[4];
#pragma unroll
    for (int i = 0; i < 4; i++) {
        int idx = tid + (i << 8);
        int r = idx >> 3, c = idx & 7;
        adst[i] = (uint32_t)(r * 128 + ((c ^ (r & 7)) << 4));
        asrc[i] = g_xh + (size_t)(base + m0 + r) * H_DIM + c * 8;
    }
    uint32_t bdst[8]; const __half* bsrc[8];
    const __half* w1e = g_w1h + (size_t)e * ((size_t)H_DIM * FFN2_DIM);
#pragma unroll
    for (int i = 0; i < 8; i++) {
        int idx = tid + (i << 8);
        int r = idx >> 5, c = idx & 31;
        bdst[i] = (uint32_t)(r * 512 + ((((c & 24) | ((c ^ r) & 7))) << 4));
        int col = (c < 16) ? (n0 + c * 8) : (FFN_DIM + n0 + (c - 16) * 8);
        bsrc[i] = w1e + (size_t)r * FFN2_DIM + col;
    }

    auto load_stage = [&](int t) {
        uint32_t ab = sb + (uint32_t)(t & 3) * STAGE_BYTES;
        uint32_t bb = ab + 16384u;
        int k0 = t * 64;
#pragma unroll
        for (int i = 0; i < 4; i++) cpa16(ab + adst[i], asrc[i] + k0);
#pragma unroll
        for (int i = 0; i < 8; i++) cpa16(bb + bdst[i], bsrc[i] + (size_t)k0 * FFN2_DIM);
    };

    uint32_t aoffr = (uint32_t)((wm * 64 + (lane & 15)) * 128);
    uint32_t cxb = (uint32_t)(lane >> 4), rx = (uint32_t)(lane & 7);
    uint32_t klocal = ((lane >> 3) & 1) * 8 + (lane & 7);
    uint32_t bbase[4];
#pragma unroll
    for (int p = 0; p < 4; p++) {
        uint32_t u = (p < 2) ? (uint32_t)(wn * 4 + p * 2)
                             : (uint32_t)(16 + wn * 4 + (p - 2) * 2);
        uint32_t unit = u + (uint32_t)(lane >> 4);
        uint32_t usw = (unit & 24) | ((unit ^ (lane & 7)) & 7);
        bbase[p] = klocal * 512 + (usw << 4);
    }

    float acc[4][8][4] = {};
    uint32_t af[2][4][4], bf[2][4][4];

    load_stage(0); CPCOMMIT();
    load_stage(1); CPCOMMIT();
    load_stage(2); CPCOMMIT();

    const int NS = H_DIM / 64;  // 16
    for (int s = 0; s < NS; s++) {
        CPWAIT2();
        __syncthreads();
        if (s + 3 < NS) load_stage(s + 3);
        CPCOMMIT();
        uint32_t ab = sb + (uint32_t)(s & 3) * STAGE_BYTES;
        uint32_t bb = ab + 16384u;
        // prime kk=0 fragments
        {
            uint32_t cx = ((cxb) ^ rx) << 4;
#pragma unroll
            for (int mt = 0; mt < 4; mt++) ldm4(af[0][mt], ab + aoffr + mt * 2048 + cx);
#pragma unroll
            for (int p = 0; p < 4; p++) ldm4t(bf[0][p], bb + bbase[p]);
        }
#pragma unroll
        for (int kk = 0; kk < 4; kk++) {
            int cur = kk & 1, nxt = cur ^ 1;
            if (kk < 3) {
                uint32_t cx = ((((uint32_t)(kk + 1) << 1) + cxb) ^ rx) << 4;
#pragma unroll
                for (int mt = 0; mt < 4; mt++)
                    ldm4(af[nxt][mt], ab + aoffr + mt * 2048 + cx);
#pragma unroll
                for (int p = 0; p < 4; p++)
                    ldm4t(bf[nxt][p], bb + bbase[p] + (uint32_t)(kk + 1) * 8192);
            }
#pragma unroll
            for (int mt = 0; mt < 4; mt++)
#pragma unroll
                for (int p = 0; p < 4; p++) {
                    mma16(acc[mt][2 * p],     af[cur][mt], bf[cur][p][0], bf[cur][p][1]);
                    mma16(acc[mt][2 * p + 1], af[cur][mt], bf[cur][p][2], bf[cur][p][3]);
                }
        }
    }

    int gid = lane >> 2, tig = lane & 3;
#pragma unroll
    for (int mt = 0; mt < 4; mt++) {
        int r1 = m0 + wm * 64 + mt * 16 + gid;
#pragma unroll
        for (int j = 0; j < 4; j++) {
            int col = n0 + wn * 32 + j * 8 + tig * 2;
            float g0 = acc[mt][j][0], g1 = acc[mt][j][1];
            float u0 = acc[mt][j + 4][0], u1 = acc[mt][j + 4][1];
            if (r1 < cnt) {
                __half2 h = __floats2half2_rn(g0 * u0 / (1.f + __expf(-g0)),
                                              g1 * u1 / (1.f + __expf(-g1)));
                *(__half2*)&g_acth[(size_t)(base + r1) * FFN_DIM + col] = h;
            }
            float g2 = acc[mt][j][2], g3 = acc[mt][j][3];
            float u2 = acc[mt][j + 4][2], u3 = acc[mt][j + 4][3];
            if (r1 + 8 < cnt) {
                __half2 h = __floats2half2_rn(g2 * u2 / (1.f + __expf(-g2)),
                                              g3 * u3 / (1.f + __expf(-g3)));
                *(__half2*)&g_acth[(size_t)(base + r1 + 8) * FFN_DIM + col] = h;
            }
        }
    }
}

// ---------------- GEMM2: g_acth[128,1408] @ w2h([k][n]) -> g_y --------------
// CTA: 128 M x 256 N; 8 warps (2m x 4n), warp tile 64x64. Fragment dbl-buffer.
__global__ void __launch_bounds__(256) gemm2_kernel()
{
    int e = blockIdx.z;
    int cnt = g_cnt[e];
    int m0 = blockIdx.y * 128;
    if (m0 >= cnt) return;
    int base = g_base[e];
    int n0 = blockIdx.x * 256;

    extern __shared__ char smem[];
    uint32_t sb = smem_u32(smem);
    int tid = threadIdx.x, lane = tid & 31, wid = tid >> 5;
    int wm = wid >> 2, wn = wid & 3;

    uint32_t adst[4]; const __half* asrc[4];
#pragma unroll
    for (int i = 0; i < 4; i++) {
        int idx = tid + (i << 8);
        int r = idx >> 3, c = idx & 7;
        adst[i] = (uint32_t)(r * 128 + ((c ^ (r & 7)) << 4));
        asrc[i] = g_acth + (size_t)(base + m0 + r) * FFN_DIM + c * 8;
    }
    uint32_t bdst[8]; const __half* bsrc[8];
    const __half* w2e = g_w2h + (size_t)e * ((size_t)FFN_DIM * H_DIM);
#pragma unroll
    for (int i = 0; i < 8; i++) {
        int idx = tid + (i << 8);
        int r = idx >> 5, c = idx & 31;
        bdst[i] = (uint32_t)(r * 512 + ((((c & 24) | ((c ^ r) & 7))) << 4));
        bsrc[i] = w2e + (size_t)r * H_DIM + n0 + c * 8;
    }

    auto load_stage = [&](int t) {
        uint32_t ab = sb + (uint32_t)(t & 3) * STAGE_BYTES;
        uint32_t bb = ab + 16384u;
        int k0 = t * 64;
#pragma unroll
        for (int i = 0; i < 4; i++) cpa16(ab + adst[i], asrc[i] + k0);
#pragma unroll
        for (int i = 0; i < 8; i++) cpa16(bb + bdst[i], bsrc[i] + (size_t)k0 * H_DIM);
    };

    uint32_t aoffr = (uint32_t)((wm * 64 + (lane & 15)) * 128);
    uint32_t cxb = (uint32_t)(lane >> 4), rx = (uint32_t)(lane & 7);
    uint32_t klocal = ((lane >> 3) & 1) * 8 + (lane & 7);
    uint32_t bbase[4];
#pragma unroll
    for (int p = 0; p < 4; p++) {
        uint32_t unit = (uint32_t)(wn * 8 + p * 2) + (uint32_t)(lane >> 4);
        uint32_t usw = (unit & 24) | ((unit ^ (lane & 7)) & 7);
        bbase[p] = klocal * 512 + (usw << 4);
    }

    float acc[4][8][4] = {};
    uint32_t af[2][4][4], bf[2][4][4];

    load_stage(0); CPCOMMIT();
    load_stage(1); CPCOMMIT();
    load_stage(2); CPCOMMIT();

    const int NS = FFN_DIM / 64;  // 22
    for (int s = 0; s < NS; s++) {
        CPWAIT2();
        __syncthreads();
        if (s + 3 < NS) load_stage(s + 3);
        CPCOMMIT();
        uint32_t ab = sb + (uint32_t)(s & 3) * STAGE_BYTES;
        uint32_t bb = ab + 16384u;
        {
            uint32_t cx = ((cxb) ^ rx) << 4;
#pragma unroll
            for (int mt = 0; mt < 4; mt++) ldm4(af[0][mt], ab + aoffr + mt * 2048 + cx);
#pragma unroll
            for (int p = 0; p < 4; p++) ldm4t(bf[0][p], bb + bbase[p]);
        }
#pragma unroll
        for (int kk = 0; kk < 4; kk++) {
            int cur = kk & 1, nxt = cur ^ 1;
            if (kk < 3) {
                uint32_t cx = ((((uint32_t)(kk + 1) << 1) + cxb) ^ rx) << 4;
#pragma unroll
                for (int mt = 0; mt < 4; mt++)
                    ldm4(af[nxt][mt], ab + aoffr + mt * 2048 + cx);
#pragma unroll
                for (int p = 0; p < 4; p++)
                    ldm4t(bf[nxt][p], bb + bbase[p] + (uint32_t)(kk + 1) * 8192);
            }
#pragma unroll
            for (int mt = 0; mt < 4; mt++)
#pragma unroll
                for (int p = 0; p < 4; p++) {
                    mma16(acc[mt][2 * p],     af[cur][mt], bf[cur][p][0], bf[cur][p][1]);
                    mma16(acc[mt][2 * p + 1], af[cur][mt], bf[cur][p][2], bf[cur][p][3]);
                }
        }
    }

    int gid = lane >> 2, tig = lane & 3;
#pragma unroll
    for (int mt = 0; mt < 4; mt++) {
        int r1 = m0 + wm * 64 + mt * 16 + gid;
#pragma unroll
        for (int j = 0; j < 8; j++) {
            int col = n0 + wn * 64 + j * 8 + tig * 2;
            if (r1 < cnt) {
                float2 o = make_float2(acc[mt][j][0], acc[mt][j][1]);
                *(float2*)&g_y[(size_t)(base + r1) * H_DIM + col] = o;
            }
            if (r1 + 8 < cnt) {
                float2 o = make_float2(acc[mt][j][2], acc[mt][j][3]);
                *(float2*)&g_y[(size_t)(base + r1 + 8) * H_DIM + col] = o;
            }
        }
    }
}

// ---------------- combine: out[t] = w0*Y[slot0] + w1*Y[slot1] --------------
__global__ void __launch_bounds__(256) combine_kernel(float* __restrict__ out)
{
    int t = blockIdx.x;
    int s0 = g_slot[2 * t], s1 = g_slot[2 * t + 1];
    float w0 = g_topk_w[2 * t], w1 = g_topk_w[2 * t + 1];
    const float* y0 = g_y + (size_t)s0 * H_DIM;
    const float* y1 = g_y + (size_t)s1 * H_DIM;
    float* orow = out + (size_t)t * H_DIM;

    int h = threadIdx.x * 4;
    float4 a = *(const float4*)(y0 + h);
    float4 b = *(const float4*)(y1 + h);
    float4 o;
    o.x = w0 * a.x + w1 * b.x;
    o.y = w0 * a.y + w1 * b.y;
    o.z = w0 * a.z + w1 * b.z;
    o.w = w0 * a.w + w1 * b.w;
    *(float4*)(orow + h) = o;
}

// ---------------- launch ----------------------------------------------------
extern "C" void kernel_launch(void* const* d_in, const int* in_sizes, int n_in,
                              void* d_out, int out_size)
{
    const float* hidden = (const float*)d_in[0];   // [S, B, H] == [T, H]
    const float* gate_w = (const float*)d_in[1];   // [E, H]
    const float* w1     = (const float*)d_in[2];   // [E, H, 2*FFN]
    const float* w2     = (const float*)d_in[3];   // [E, FFN, H]
    float* out          = (float*)d_out;

    cudaFuncSetAttribute(gemm1_kernel, cudaFuncAttributeMaxDynamicSharedMemorySize, SMEM_BYTES);
    cudaFuncSetAttribute(gemm2_kernel, cudaFuncAttributeMaxDynamicSharedMemorySize, SMEM_BYTES);

    gate_kernel<<<T_DIM, 256>>>(hidden, gate_w);
    scatter_kernel<<<1, 256>>>();
    convW_kernel<<<4096, 256>>>(w1, w2);
    gather_kernel<<<NPAD / 4, 256>>>(hidden);
    gemm1_kernel<<<dim3(FFN_DIM / 128, NPAIR / 128, E_DIM), 256, SMEM_BYTES>>>();
    gemm2_kernel<<<dim3(H_DIM / 256, NPAIR / 128, E_DIM), 256, SMEM_BYTES>>>();
    combine_kernel<<<T_DIM, 256>>>(out);
}

// round 10
// speedup vs baseline: 1.0087x; 1.0087x over previous
#include <cuda_runtime.h>
#include <cuda_fp16.h>
#include <cstdint>

// Problem shapes (fixed by the dataset)
#define T_DIM 2048
#define H_DIM 1024
#define E_DIM 8
#define FFN_DIM 1408
#define FFN2_DIM 2816
#define NPAIR 4096
#define NPAD (NPAIR + 128)

// ---------------- scratch (device globals) ----------------------------------
__device__ int   g_topk_idx[T_DIM * 2];
__device__ float g_topk_w[T_DIM * 2];
__device__ int   g_tok[NPAIR];
__device__ int   g_slot[T_DIM * 2];
__device__ int   g_base[E_DIM];
__device__ int   g_cnt[E_DIM];
__device__ __align__(16) __half g_xh[(size_t)NPAD * H_DIM];
__device__ __align__(16) __half g_acth[(size_t)NPAD * FFN_DIM];
__device__ __align__(16) float  g_y[(size_t)NPAIR * H_DIM];
__device__ __align__(16) __half g_w1h[(size_t)E_DIM * H_DIM * FFN2_DIM];   // native [k][n]
__device__ __align__(16) __half g_w2h[(size_t)E_DIM * FFN_DIM * H_DIM];    // native [k][n]

// ---------------- helpers ----------------------------------------------------
__device__ __forceinline__ uint32_t smem_u32(const void* p) {
    uint32_t a;
    asm("{ .reg .u64 t; cvta.to.shared.u64 t, %1; cvt.u32.u64 %0, t; }"
        : "=r"(a) : "l"(p));
    return a;
}
__device__ __forceinline__ void cpa16(uint32_t dst, const void* src) {
    asm volatile("cp.async.cg.shared.global [%0], [%1], 16;" :: "r"(dst), "l"(src));
}
#define CPCOMMIT() asm volatile("cp.async.commit_group;" ::: "memory")
#define CPWAIT2()  asm volatile("cp.async.wait_group 2;" ::: "memory")

__device__ __forceinline__ void ldm4(uint32_t* f, uint32_t a) {
    asm volatile("ldmatrix.sync.aligned.m8n8.x4.shared.b16 {%0,%1,%2,%3}, [%4];"
                 : "=r"(f[0]), "=r"(f[1]), "=r"(f[2]), "=r"(f[3]) : "r"(a));
}
__device__ __forceinline__ void ldm4t(uint32_t* f, uint32_t a) {
    asm volatile("ldmatrix.sync.aligned.m8n8.x4.trans.shared.b16 {%0,%1,%2,%3}, [%4];"
                 : "=r"(f[0]), "=r"(f[1]), "=r"(f[2]), "=r"(f[3]) : "r"(a));
}
__device__ __forceinline__ void mma16(float* c, const uint32_t* a,
                                      uint32_t b0, uint32_t b1) {
    asm volatile(
        "mma.sync.aligned.m16n8k16.row.col.f32.f16.f16.f32 "
        "{%0,%1,%2,%3}, {%4,%5,%6,%7}, {%8,%9}, {%0,%1,%2,%3};"
        : "+f"(c[0]), "+f"(c[1]), "+f"(c[2]), "+f"(c[3])
        : "r"(a[0]), "r"(a[1]), "r"(a[2]), "r"(a[3]), "r"(b0), "r"(b1));
}

// stage: A [128 m][64 k] half = 16KB at +0 ; B [64 k][256 n] half = 32KB at +16384
#define STAGE_BYTES 49152u
#define NSTAGE 4
#define SMEM_BYTES (NSTAGE * STAGE_BYTES)   // 196608

// ---------------- gate: softmax(x @ gate_w^T), top-2, renormalize ----------
__global__ void __launch_bounds__(256) gate_kernel(
    const float* __restrict__ x, const float* __restrict__ gw)
{
    int t = blockIdx.x;
    const float* xr = x + (size_t)t * H_DIM;
    int wid = threadIdx.x >> 5, lane = threadIdx.x & 31;
    __shared__ float sc[E_DIM];

    const float* g = gw + (size_t)wid * H_DIM;
    float s = 0.f;
    for (int i = lane; i < H_DIM; i += 32) s += xr[i] * g[i];
#pragma unroll
    for (int o = 16; o; o >>= 1) s += __shfl_xor_sync(0xffffffffu, s, o);
    if (lane == 0) sc[wid] = s;
    __syncthreads();

    if (threadIdx.x == 0) {
        float m = -1e30f;
#pragma unroll
        for (int e = 0; e < E_DIM; e++) m = fmaxf(m, sc[e]);
        float p[E_DIM], den = 0.f;
#pragma unroll
        for (int e = 0; e < E_DIM; e++) { p[e] = __expf(sc[e] - m); den += p[e]; }
        int i0 = 0;
#pragma unroll
        for (int e = 1; e < E_DIM; e++) if (p[e] > p[i0]) i0 = e;
        int i1 = -1;
#pragma unroll
        for (int e = 0; e < E_DIM; e++)
            if (e != i0 && (i1 < 0 || p[e] > p[i1])) i1 = e;
        float q0 = p[i0] / den, q1 = p[i1] / den;
        float wsum = q0 + q1 + 1e-20f;
        g_topk_idx[2 * t]     = i0;
        g_topk_idx[2 * t + 1] = i1;
        g_topk_w[2 * t]       = q0 / wsum;
        g_topk_w[2 * t + 1]   = q1 / wsum;
    }
}

// ---------------- scatter: deterministic compaction by expert --------------
__global__ void __launch_bounds__(256) scatter_kernel()
{
    int wid = threadIdx.x >> 5, lane = threadIdx.x & 31;
    __shared__ int scnt[E_DIM];

    int c = 0;
    for (int baset = 0; baset < T_DIM; baset += 32) {
        int t = baset + lane;
        bool m = (g_topk_idx[2 * t] == wid) || (g_topk_idx[2 * t + 1] == wid);
        unsigned b = __ballot_sync(0xffffffffu, m);
        c += __popc(b);
    }
    if (lane == 0) scnt[wid] = c;
    __syncthreads();
    if (threadIdx.x == 0) {
        int acc = 0;
        for (int e = 0; e < E_DIM; e++) { g_base[e] = acc; g_cnt[e] = scnt[e]; acc += scnt[e]; }
    }
    __syncthreads();

    int pos = g_base[wid];
    for (int baset = 0; baset < T_DIM; baset += 32) {
        int t = baset + lane;
        int k = -1;
        if (g_topk_idx[2 * t] == wid) k = 0;
        else if (g_topk_idx[2 * t + 1] == wid) k = 1;
        unsigned b = __ballot_sync(0xffffffffu, k >= 0);
        int off = __popc(b & ((1u << lane) - 1u));
        if (k >= 0) {
            g_tok[pos + off] = t;
            g_slot[2 * t + k] = pos + off;
        }
        pos += __popc(b);
    }
}

// ---------------- gather rows -> g_xh (half); 4 rows/block, MLP=4 -----------
__global__ void __launch_bounds__(256) gather_kernel(const float* __restrict__ x)
{
    int p0 = blockIdx.x * 4;
    const float4* src[4];
    float4 v[4];
#pragma unroll
    for (int j = 0; j < 4; j++) {
        int p = p0 + j;
        int t = (p < NPAIR) ? g_tok[p] : 0;
        src[j] = (const float4*)(x + (size_t)t * H_DIM);
    }
#pragma unroll
    for (int j = 0; j < 4; j++) v[j] = src[j][threadIdx.x];
#pragma unroll
    for (int j = 0; j < 4; j++) {
        __half2* d = (__half2*)(g_xh + (size_t)(p0 + j) * H_DIM);
        d[threadIdx.x * 2]     = __floats2half2_rn(v[j].x, v[j].y);
        d[threadIdx.x * 2 + 1] = __floats2half2_rn(v[j].z, v[j].w);
    }
}

// ---------------- streaming f32 -> f16 cast for BOTH weights ----------------
__global__ void __launch_bounds__(256) convW_kernel(
    const float* __restrict__ w1, const float* __restrict__ w2)
{
    const size_t n1 = (size_t)E_DIM * H_DIM * FFN2_DIM / 4;
    const size_t n2 = (size_t)E_DIM * FFN_DIM * H_DIM / 4;
    size_t i = (size_t)blockIdx.x * blockDim.x + threadIdx.x;
    size_t stride = (size_t)gridDim.x * blockDim.x;
    for (; i < n1 + n2; i += stride) {
        const float4* s;
        uint2* d;
        size_t k;
        if (i < n1) { s = (const float4*)w1; d = (uint2*)g_w1h; k = i; }
        else        { s = (const float4*)w2; d = (uint2*)g_w2h; k = i - n1; }
        float4 v = s[k];
        __half2 h0 = __floats2half2_rn(v.x, v.y);
        __half2 h1 = __floats2half2_rn(v.z, v.w);
        d[k] = make_uint2(*(uint32_t*)&h0, *(uint32_t*)&h1);
    }
}

// ---------------- GEMM1: g_xh[128,1024] @ w1h([k][n]) -> swiglu -> g_acth ---
// CTA: 128 M x 128 FFN cols; B stage [64k][256n] (gate cols 0-127, up 128-255).
// 8 warps (2m x 4n), warp tile 64 x 64 (32 gate + 32 up FFN cols).
__global__ void __launch_bounds__(256) gemm1_kernel()
{
    int e = blockIdx.z;
    int cnt = g_cnt[e];
    int m0 = blockIdx.y * 128;
    if (m0 >= cnt) return;
    int base = g_base[e];
    int n0 = blockIdx.x * 128;

    extern __shared__ char smem[];
    uint32_t sb = smem_u32(smem);
    int tid = threadIdx.x, lane = tid & 31, wid = tid >> 5;
    int wm = wid >> 2, wn = wid & 3;

    uint32_t adst[4]; const __half* asrc[4];
#pragma unroll
    for (int i = 0; i < 4; i++) {
        int idx = tid + (i << 8);
        int r = idx >> 3, c = idx & 7;
        adst[i] = (uint32_t)(r * 128 + ((c ^ (r & 7)) << 4));
        asrc[i] = g_xh + (size_t)(base + m0 + r) * H_DIM + c * 8;
    }
    uint32_t bdst[8]; const __half* bsrc[8];
    const __half* w1e = g_w1h + (size_t)e * ((size_t)H_DIM * FFN2_DIM);
#pragma unroll
    for (int i = 0; i < 8; i++) {
        int idx = tid + (i << 8);
        int r = idx >> 5, c = idx & 31;
        bdst[i] = (uint32_t)(r * 512 + ((((c & 24) | ((c ^ r) & 7))) << 4));
        int col = (c < 16) ? (n0 + c * 8) : (FFN_DIM + n0 + (c - 16) * 8);
        bsrc[i] = w1e + (size_t)r * FFN2_DIM + col;
    }

    auto load_stage = [&](int t) {
        uint32_t ab = sb + (uint32_t)(t & 3) * STAGE_BYTES;
        uint32_t bb = ab + 16384u;
        int k0 = t * 64;
#pragma unroll
        for (int i = 0; i < 4; i++) cpa16(ab + adst[i], asrc[i] + k0);
#pragma unroll
        for (int i = 0; i < 8; i++) cpa16(bb + bdst[i], bsrc[i] + (size_t)k0 * FFN2_DIM);
    };

    uint32_t aoffr = (uint32_t)((wm * 64 + (lane & 15)) * 128);
    uint32_t cxb = (uint32_t)(lane >> 4), rx = (uint32_t)(lane & 7);
    uint32_t klocal = ((lane >> 3) & 1) * 8 + (lane & 7);
    uint32_t bbase[4];
#pragma unroll
    for (int p = 0; p < 4; p++) {
        uint32_t u = (p < 2) ? (uint32_t)(wn * 4 + p * 2)
                             : (uint32_t)(16 + wn * 4 + (p - 2) * 2);
        uint32_t unit = u + (uint32_t)(lane >> 4);
        uint32_t usw = (unit & 24) | ((unit ^ (lane & 7)) & 7);
        bbase[p] = klocal * 512 + (usw << 4);
    }

    float acc[4][8][4] = {};

    load_stage(0); CPCOMMIT();
    load_stage(1); CPCOMMIT();
    load_stage(2); CPCOMMIT();

    const int NS = H_DIM / 64;  // 16
    for (int s = 0; s < NS; s++) {
        CPWAIT2();
        __syncthreads();
        if (s + 3 < NS) load_stage(s + 3);
        CPCOMMIT();
        uint32_t ab = sb + (uint32_t)(s & 3) * STAGE_BYTES;
        uint32_t bb = ab + 16384u;
#pragma unroll
        for (int kk = 0; kk < 4; kk++) {
            uint32_t cx = ((((uint32_t)kk << 1) + cxb) ^ rx) << 4;
            uint32_t af[4][4], bf[4][4];
#pragma unroll
            for (int mt = 0; mt < 4; mt++) ldm4(af[mt], ab + aoffr + mt * 2048 + cx);
#pragma unroll
            for (int p = 0; p < 4; p++) ldm4t(bf[p], bb + bbase[p] + (uint32_t)kk * 8192);
#pragma unroll
            for (int mt = 0; mt < 4; mt++)
#pragma unroll
                for (int p = 0; p < 4; p++) {
                    mma16(acc[mt][2 * p],     af[mt], bf[p][0], bf[p][1]);
                    mma16(acc[mt][2 * p + 1], af[mt], bf[p][2], bf[p][3]);
                }
        }
    }

    // epilogue: swiglu, store half
    int gid = lane >> 2, tig = lane & 3;
#pragma unroll
    for (int mt = 0; mt < 4; mt++) {
        int r1 = m0 + wm * 64 + mt * 16 + gid;
#pragma unroll
        for (int j = 0; j < 4; j++) {
            int col = n0 + wn * 32 + j * 8 + tig * 2;
            float g0 = acc[mt][j][0], g1 = acc[mt][j][1];
            float u0 = acc[mt][j + 4][0], u1 = acc[mt][j + 4][1];
            if (r1 < cnt) {
                __half2 h = __floats2half2_rn(g0 * u0 / (1.f + __expf(-g0)),
                                              g1 * u1 / (1.f + __expf(-g1)));
                *(__half2*)&g_acth[(size_t)(base + r1) * FFN_DIM + col] = h;
            }
            float g2 = acc[mt][j][2], g3 = acc[mt][j][3];
            float u2 = acc[mt][j + 4][2], u3 = acc[mt][j + 4][3];
            if (r1 + 8 < cnt) {
                __half2 h = __floats2half2_rn(g2 * u2 / (1.f + __expf(-g2)),
                                              g3 * u3 / (1.f + __expf(-g3)));
                *(__half2*)&g_acth[(size_t)(base + r1 + 8) * FFN_DIM + col] = h;
            }
        }
    }
}

// ---------------- GEMM2: g_acth[128,1408] @ w2h([k][n]) -> g_y --------------
// CTA: 128 M x 256 N; 8 warps (2m x 4n), warp tile 64x64.
__global__ void __launch_bounds__(256) gemm2_kernel()
{
    int e = blockIdx.z;
    int cnt = g_cnt[e];
    int m0 = blockIdx.y * 128;
    if (m0 >= cnt) return;
    int base = g_base[e];
    int n0 = blockIdx.x * 256;

    extern __shared__ char smem[];
    uint32_t sb = smem_u32(smem);
    int tid = threadIdx.x, lane = tid & 31, wid = tid >> 5;
    int wm = wid >> 2, wn = wid & 3;

    uint32_t adst[4]; const __half* asrc[4];
#pragma unroll
    for (int i = 0; i < 4; i++) {
        int idx = tid + (i << 8);
        int r = idx >> 3, c = idx & 7;
        adst[i] = (uint32_t)(r * 128 + ((c ^ (r & 7)) << 4));
        asrc[i] = g_acth + (size_t)(base + m0 + r) * FFN_DIM + c * 8;
    }
    uint32_t bdst[8]; const __half* bsrc[8];
    const __half* w2e = g_w2h + (size_t)e * ((size_t)FFN_DIM * H_DIM);
#pragma unroll
    for (int i = 0; i < 8; i++) {
        int idx = tid + (i << 8);
        int r = idx >> 5, c = idx & 31;
        bdst[i] = (uint32_t)(r * 512 + ((((c & 24) | ((c ^ r) & 7))) << 4));
        bsrc[i] = w2e + (size_t)r * H_DIM + n0 + c * 8;
    }

    auto load_stage = [&](int t) {
        uint32_t ab = sb + (uint32_t)(t & 3) * STAGE_BYTES;
        uint32_t bb = ab + 16384u;
        int k0 = t * 64;
#pragma unroll
        for (int i = 0; i < 4; i++) cpa16(ab + adst[i], asrc[i] + k0);
#pragma unroll
        for (int i = 0; i < 8; i++) cpa16(bb + bdst[i], bsrc[i] + (size_t)k0 * H_DIM);
    };

    uint32_t aoffr = (uint32_t)((wm * 64 + (lane & 15)) * 128);
    uint32_t cxb = (uint32_t)(lane >> 4), rx = (uint32_t)(lane & 7);
    uint32_t klocal = ((lane >> 3) & 1) * 8 + (lane & 7);
    uint32_t bbase[4];
#pragma unroll
    for (int p = 0; p < 4; p++) {
        uint32_t unit = (uint32_t)(wn * 8 + p * 2) + (uint32_t)(lane >> 4);
        uint32_t usw = (unit & 24) | ((unit ^ (lane & 7)) & 7);
        bbase[p] = klocal * 512 + (usw << 4);
    }

    float acc[4][8][4] = {};

    load_stage(0); CPCOMMIT();
    load_stage(1); CPCOMMIT();
    load_stage(2); CPCOMMIT();

    const int NS = FFN_DIM / 64;  // 22
    for (int s = 0; s < NS; s++) {
        CPWAIT2();
        __syncthreads();
        if (s + 3 < NS) load_stage(s + 3);
        CPCOMMIT();
        uint32_t ab = sb + (uint32_t)(s & 3) * STAGE_BYTES;
        uint32_t bb = ab + 16384u;
#pragma unroll
        for (int kk = 0; kk < 4; kk++) {
            uint32_t cx = ((((uint32_t)kk << 1) + cxb) ^ rx) << 4;
            uint32_t af[4][4], bf[4][4];
#pragma unroll
            for (int mt = 0; mt < 4; mt++) ldm4(af[mt], ab + aoffr + mt * 2048 + cx);
#pragma unroll
            for (int p = 0; p < 4; p++) ldm4t(bf[p], bb + bbase[p] + (uint32_t)kk * 8192);
#pragma unroll
            for (int mt = 0; mt < 4; mt++)
#pragma unroll
                for (int p = 0; p < 4; p++) {
                    mma16(acc[mt][2 * p],     af[mt], bf[p][0], bf[p][1]);
                    mma16(acc[mt][2 * p + 1], af[mt], bf[p][2], bf[p][3]);
                }
        }
    }

    int gid = lane >> 2, tig = lane & 3;
#pragma unroll
    for (int mt = 0; mt < 4; mt++) {
        int r1 = m0 + wm * 64 + mt * 16 + gid;
#pragma unroll
        for (int j = 0; j < 8; j++) {
            int col = n0 + wn * 64 + j * 8 + tig * 2;
            if (r1 < cnt) {
                float2 o = make_float2(acc[mt][j][0], acc[mt][j][1]);
                *(float2*)&g_y[(size_t)(base + r1) * H_DIM + col] = o;
            }
            if (r1 + 8 < cnt) {
                float2 o = make_float2(acc[mt][j][2], acc[mt][j][3]);
                *(float2*)&g_y[(size_t)(base + r1 + 8) * H_DIM + col] = o;
            }
        }
    }
}

// ---------------- combine: out[t] = w0*Y[slot0] + w1*Y[slot1] --------------
__global__ void __launch_bounds__(256) combine_kernel(float* __restrict__ out)
{
    int t = blockIdx.x;
    int s0 = g_slot[2 * t], s1 = g_slot[2 * t + 1];
    float w0 = g_topk_w[2 * t], w1 = g_topk_w[2 * t + 1];
    const float* y0 = g_y + (size_t)s0 * H_DIM;
    const float* y1 = g_y + (size_t)s1 * H_DIM;
    float* orow = out + (size_t)t * H_DIM;

    int h = threadIdx.x * 4;
    float4 a = *(const float4*)(y0 + h);
    float4 b = *(const float4*)(y1 + h);
    float4 o;
    o.x = w0 * a.x + w1 * b.x;
    o.y = w0 * a.y + w1 * b.y;
    o.z = w0 * a.z + w1 * b.z;
    o.w = w0 * a.w + w1 * b.w;
    *(float4*)(orow + h) = o;
}

// ---------------- launch ----------------------------------------------------
extern "C" void kernel_launch(void* const* d_in, const int* in_sizes, int n_in,
                              void* d_out, int out_size)
{
    const float* hidden = (const float*)d_in[0];   // [S, B, H] == [T, H]
    const float* gate_w = (const float*)d_in[1];   // [E, H]
    const float* w1     = (const float*)d_in[2];   // [E, H, 2*FFN]
    const float* w2     = (const float*)d_in[3];   // [E, FFN, H]
    float* out          = (float*)d_out;

    // One-time host resources (created on the correctness call, before graph
    // capture; reused identically every call -> deterministic work).
    static cudaStream_t s2 = nullptr;
    static cudaEvent_t ev_fork = nullptr, ev_join = nullptr;
    static bool attr_done = false;
    if (!s2) {
        cudaStreamCreateWithFlags(&s2, cudaStreamNonBlocking);
        cudaEventCreateWithFlags(&ev_fork, cudaEventDisableTiming);
        cudaEventCreateWithFlags(&ev_join, cudaEventDisableTiming);
    }
    if (!attr_done) {
        cudaFuncSetAttribute(gemm1_kernel, cudaFuncAttributeMaxDynamicSharedMemorySize, SMEM_BYTES);
        cudaFuncSetAttribute(gemm2_kernel, cudaFuncAttributeMaxDynamicSharedMemorySize, SMEM_BYTES);
        attr_done = true;
    }

    // Fork: weight conversion runs concurrently with gate/scatter/gather.
    cudaEventRecord(ev_fork, 0);
    cudaStreamWaitEvent(s2, ev_fork, 0);
    convW_kernel<<<4096, 256, 0, s2>>>(w1, w2);
    cudaEventRecord(ev_join, s2);

    gate_kernel<<<T_DIM, 256>>>(hidden, gate_w);
    scatter_kernel<<<1, 256>>>();
    gather_kernel<<<NPAD / 4, 256>>>(hidden);

    // Join: GEMMs need both branches.
    cudaStreamWaitEvent(0, ev_join, 0);
    gemm1_kernel<<<dim3(FFN_DIM / 128, NPAIR / 128, E_DIM), 256, SMEM_BYTES>>>();
    gemm2_kernel<<<dim3(H_DIM / 256, NPAIR / 128, E_DIM), 256, SMEM_BYTES>>>();
    combine_kernel<<<T_DIM, 256>>>(out);
}

// round 11
// speedup vs baseline: 1.0328x; 1.0239x over previous
#include <cuda_runtime.h>
#include <cuda_fp16.h>
#include <cstdint>

// Problem shapes (fixed by the dataset)
#define T_DIM 2048
#define H_DIM 1024
#define E_DIM 8
#define FFN_DIM 1408
#define FFN2_DIM 2816
#define NPAIR 4096
#define NPAD (NPAIR + 128)

// ---------------- scratch (device globals) ----------------------------------
__device__ int   g_topk_idx[T_DIM * 2];
__device__ float g_topk_w[T_DIM * 2];
__device__ int   g_tok[NPAIR];
__device__ int   g_slot[T_DIM * 2];
__device__ int   g_base[E_DIM];
__device__ int   g_cnt[E_DIM];
__device__ __align__(16) __half g_xh[(size_t)T_DIM * H_DIM];               // token rows (half)
__device__ __align__(16) __half g_acth[(size_t)NPAD * FFN_DIM];
__device__ __align__(16) float  g_y[(size_t)NPAIR * H_DIM];
__device__ __align__(16) __half g_w1h[(size_t)E_DIM * H_DIM * FFN2_DIM];   // native [k][n]
__device__ __align__(16) __half g_w2h[(size_t)E_DIM * FFN_DIM * H_DIM];    // native [k][n]

// ---------------- helpers ----------------------------------------------------
__device__ __forceinline__ uint32_t smem_u32(const void* p) {
    uint32_t a;
    asm("{ .reg .u64 t; cvta.to.shared.u64 t, %1; cvt.u32.u64 %0, t; }"
        : "=r"(a) : "l"(p));
    return a;
}
__device__ __forceinline__ void cpa16(uint32_t dst, const void* src) {
    asm volatile("cp.async.cg.shared.global [%0], [%1], 16;" :: "r"(dst), "l"(src));
}
#define CPCOMMIT() asm volatile("cp.async.commit_group;" ::: "memory")
#define CPWAIT2()  asm volatile("cp.async.wait_group 2;" ::: "memory")

__device__ __forceinline__ void ldm4(uint32_t* f, uint32_t a) {
    asm volatile("ldmatrix.sync.aligned.m8n8.x4.shared.b16 {%0,%1,%2,%3}, [%4];"
                 : "=r"(f[0]), "=r"(f[1]), "=r"(f[2]), "=r"(f[3]) : "r"(a));
}
__device__ __forceinline__ void ldm4t(uint32_t* f, uint32_t a) {
    asm volatile("ldmatrix.sync.aligned.m8n8.x4.trans.shared.b16 {%0,%1,%2,%3}, [%4];"
                 : "=r"(f[0]), "=r"(f[1]), "=r"(f[2]), "=r"(f[3]) : "r"(a));
}
__device__ __forceinline__ void mma16(float* c, const uint32_t* a,
                                      uint32_t b0, uint32_t b1) {
    asm volatile(
        "mma.sync.aligned.m16n8k16.row.col.f32.f16.f16.f32 "
        "{%0,%1,%2,%3}, {%4,%5,%6,%7}, {%8,%9}, {%0,%1,%2,%3};"
        : "+f"(c[0]), "+f"(c[1]), "+f"(c[2]), "+f"(c[3])
        : "r"(a[0]), "r"(a[1]), "r"(a[2]), "r"(a[3]), "r"(b0), "r"(b1));
}

// stage: A [128 m][64 k] half = 16KB at +0 ; B [64 k][256 n] half = 32KB at +16384
#define STAGE_BYTES 49152u
#define NSTAGE 4
#define SMEM_BYTES (NSTAGE * STAGE_BYTES)   // 196608

// ---------------- gate: softmax top-2 + half conversion of the token row ----
__global__ void __launch_bounds__(256) gate_kernel(
    const float* __restrict__ x, const float* __restrict__ gw)
{
    int t = blockIdx.x;
    const float* xr = x + (size_t)t * H_DIM;
    int wid = threadIdx.x >> 5, lane = threadIdx.x & 31;
    __shared__ float sc[E_DIM];

    // fused f32 -> f16 conversion of this token row (one float4 per thread)
    {
        float4 v = ((const float4*)xr)[threadIdx.x];
        __half2* d = (__half2*)(g_xh + (size_t)t * H_DIM);
        d[threadIdx.x * 2]     = __floats2half2_rn(v.x, v.y);
        d[threadIdx.x * 2 + 1] = __floats2half2_rn(v.z, v.w);
    }

    const float* g = gw + (size_t)wid * H_DIM;
    float s = 0.f;
    for (int i = lane; i < H_DIM; i += 32) s += xr[i] * g[i];
#pragma unroll
    for (int o = 16; o; o >>= 1) s += __shfl_xor_sync(0xffffffffu, s, o);
    if (lane == 0) sc[wid] = s;
    __syncthreads();

    if (threadIdx.x == 0) {
        float m = -1e30f;
#pragma unroll
        for (int e = 0; e < E_DIM; e++) m = fmaxf(m, sc[e]);
        float p[E_DIM], den = 0.f;
#pragma unroll
        for (int e = 0; e < E_DIM; e++) { p[e] = __expf(sc[e] - m); den += p[e]; }
        int i0 = 0;
#pragma unroll
        for (int e = 1; e < E_DIM; e++) if (p[e] > p[i0]) i0 = e;
        int i1 = -1;
#pragma unroll
        for (int e = 0; e < E_DIM; e++)
            if (e != i0 && (i1 < 0 || p[e] > p[i1])) i1 = e;
        float q0 = p[i0] / den, q1 = p[i1] / den;
        float wsum = q0 + q1 + 1e-20f;
        g_topk_idx[2 * t]     = i0;
        g_topk_idx[2 * t + 1] = i1;
        g_topk_w[2 * t]       = q0 / wsum;
        g_topk_w[2 * t + 1]   = q1 / wsum;
    }
}

// ---------------- scatter: deterministic compaction by expert --------------
__global__ void __launch_bounds__(256) scatter_kernel()
{
    int wid = threadIdx.x >> 5, lane = threadIdx.x & 31;
    __shared__ int scnt[E_DIM];

    int c = 0;
    for (int baset = 0; baset < T_DIM; baset += 32) {
        int t = baset + lane;
        bool m = (g_topk_idx[2 * t] == wid) || (g_topk_idx[2 * t + 1] == wid);
        unsigned b = __ballot_sync(0xffffffffu, m);
        c += __popc(b);
    }
    if (lane == 0) scnt[wid] = c;
    __syncthreads();
    if (threadIdx.x == 0) {
        int acc = 0;
        for (int e = 0; e < E_DIM; e++) { g_base[e] = acc; g_cnt[e] = scnt[e]; acc += scnt[e]; }
    }
    __syncthreads();

    int pos = g_base[wid];
    for (int baset = 0; baset < T_DIM; baset += 32) {
        int t = baset + lane;
        int k = -1;
        if (g_topk_idx[2 * t] == wid) k = 0;
        else if (g_topk_idx[2 * t + 1] == wid) k = 1;
        unsigned b = __ballot_sync(0xffffffffu, k >= 0);
        int off = __popc(b & ((1u << lane) - 1u));
        if (k >= 0) {
            g_tok[pos + off] = t;
            g_slot[2 * t + k] = pos + off;
        }
        pos += __popc(b);
    }
}

// ---------------- streaming f32 -> f16 cast for BOTH weights ----------------
__global__ void __launch_bounds__(256) convW_kernel(
    const float* __restrict__ w1, const float* __restrict__ w2)
{
    const size_t n1 = (size_t)E_DIM * H_DIM * FFN2_DIM / 4;
    const size_t n2 = (size_t)E_DIM * FFN_DIM * H_DIM / 4;
    size_t i = (size_t)blockIdx.x * blockDim.x + threadIdx.x;
    size_t stride = (size_t)gridDim.x * blockDim.x;
    for (; i < n1 + n2; i += stride) {
        const float4* s;
        uint2* d;
        size_t k;
        if (i < n1) { s = (const float4*)w1; d = (uint2*)g_w1h; k = i; }
        else        { s = (const float4*)w2; d = (uint2*)g_w2h; k = i - n1; }
        float4 v = s[k];
        __half2 h0 = __floats2half2_rn(v.x, v.y);
        __half2 h1 = __floats2half2_rn(v.z, v.w);
        d[k] = make_uint2(*(uint32_t*)&h0, *(uint32_t*)&h1);
    }
}

// ---------------- GEMM1: x_tok rows @ w1h([k][n]) -> swiglu -> g_acth -------
// CTA: 128 M x 128 FFN cols; B stage [64k][256n] (gate cols 0-127, up 128-255).
// 8 warps (2m x 4n), warp tile 64 x 64. A rows fetched via g_tok indirection.
__global__ void __launch_bounds__(256) gemm1_kernel()
{
    int e = blockIdx.z;
    int cnt = g_cnt[e];
    int m0 = blockIdx.y * 128;
    if (m0 >= cnt) return;
    int base = g_base[e];
    int n0 = blockIdx.x * 128;

    extern __shared__ char smem[];
    uint32_t sb = smem_u32(smem);
    int tid = threadIdx.x, lane = tid & 31, wid = tid >> 5;
    int wm = wid >> 2, wn = wid & 3;

    uint32_t adst[4]; const __half* asrc[4];
#pragma unroll
    for (int i = 0; i < 4; i++) {
        int idx = tid + (i << 8);
        int r = idx >> 3, c = idx & 7;
        adst[i] = (uint32_t)(r * 128 + ((c ^ (r & 7)) << 4));
        int pr = base + m0 + r;
        if (pr > NPAIR - 1) pr = NPAIR - 1;
        int tok = g_tok[pr];
        asrc[i] = g_xh + (size_t)tok * H_DIM + c * 8;
    }
    uint32_t bdst[8]; const __half* bsrc[8];
    const __half* w1e = g_w1h + (size_t)e * ((size_t)H_DIM * FFN2_DIM);
#pragma unroll
    for (int i = 0; i < 8; i++) {
        int idx = tid + (i << 8);
        int r = idx >> 5, c = idx & 31;
        bdst[i] = (uint32_t)(r * 512 + ((((c & 24) | ((c ^ r) & 7))) << 4));
        int col = (c < 16) ? (n0 + c * 8) : (FFN_DIM + n0 + (c - 16) * 8);
        bsrc[i] = w1e + (size_t)r * FFN2_DIM + col;
    }

    auto load_stage = [&](int t) {
        uint32_t ab = sb + (uint32_t)(t & 3) * STAGE_BYTES;
        uint32_t bb = ab + 16384u;
        int k0 = t * 64;
#pragma unroll
        for (int i = 0; i < 4; i++) cpa16(ab + adst[i], asrc[i] + k0);
#pragma unroll
        for (int i = 0; i < 8; i++) cpa16(bb + bdst[i], bsrc[i] + (size_t)k0 * FFN2_DIM);
    };

    uint32_t aoffr = (uint32_t)((wm * 64 + (lane & 15)) * 128);
    uint32_t cxb = (uint32_t)(lane >> 4), rx = (uint32_t)(lane & 7);
    uint32_t klocal = ((lane >> 3) & 1) * 8 + (lane & 7);
    uint32_t bbase[4];
#pragma unroll
    for (int p = 0; p < 4; p++) {
        uint32_t u = (p < 2) ? (uint32_t)(wn * 4 + p * 2)
                             : (uint32_t)(16 + wn * 4 + (p - 2) * 2);
        uint32_t unit = u + (uint32_t)(lane >> 4);
        uint32_t usw = (unit & 24) | ((unit ^ (lane & 7)) & 7);
        bbase[p] = klocal * 512 + (usw << 4);
    }

    float acc[4][8][4] = {};

    load_stage(0); CPCOMMIT();
    load_stage(1); CPCOMMIT();
    load_stage(2); CPCOMMIT();

    const int NS = H_DIM / 64;  // 16
    for (int s = 0; s < NS; s++) {
        CPWAIT2();
        __syncthreads();
        if (s + 3 < NS) load_stage(s + 3);
        CPCOMMIT();
        uint32_t ab = sb + (uint32_t)(s & 3) * STAGE_BYTES;
        uint32_t bb = ab + 16384u;
#pragma unroll
        for (int kk = 0; kk < 4; kk++) {
            uint32_t cx = ((((uint32_t)kk << 1) + cxb) ^ rx) << 4;
            uint32_t af[4][4], bf[4][4];
#pragma unroll
            for (int mt = 0; mt < 4; mt++) ldm4(af[mt], ab + aoffr + mt * 2048 + cx);
#pragma unroll
            for (int p = 0; p < 4; p++) ldm4t(bf[p], bb + bbase[p] + (uint32_t)kk * 8192);
#pragma unroll
            for (int mt = 0; mt < 4; mt++)
#pragma unroll
                for (int p = 0; p < 4; p++) {
                    mma16(acc[mt][2 * p],     af[mt], bf[p][0], bf[p][1]);
                    mma16(acc[mt][2 * p + 1], af[mt], bf[p][2], bf[p][3]);
                }
        }
    }

    // epilogue: swiglu, store half
    int gid = lane >> 2, tig = lane & 3;
#pragma unroll
    for (int mt = 0; mt < 4; mt++) {
        int r1 = m0 + wm * 64 + mt * 16 + gid;
#pragma unroll
        for (int j = 0; j < 4; j++) {
            int col = n0 + wn * 32 + j * 8 + tig * 2;
            float g0 = acc[mt][j][0], g1 = acc[mt][j][1];
            float u0 = acc[mt][j + 4][0], u1 = acc[mt][j + 4][1];
            if (r1 < cnt) {
                __half2 h = __floats2half2_rn(g0 * u0 / (1.f + __expf(-g0)),
                                              g1 * u1 / (1.f + __expf(-g1)));
                *(__half2*)&g_acth[(size_t)(base + r1) * FFN_DIM + col] = h;
            }
            float g2 = acc[mt][j][2], g3 = acc[mt][j][3];
            float u2 = acc[mt][j + 4][2], u3 = acc[mt][j + 4][3];
            if (r1 + 8 < cnt) {
                __half2 h = __floats2half2_rn(g2 * u2 / (1.f + __expf(-g2)),
                                              g3 * u3 / (1.f + __expf(-g3)));
                *(__half2*)&g_acth[(size_t)(base + r1 + 8) * FFN_DIM + col] = h;
            }
        }
    }
}

// ---------------- GEMM2: g_acth[128,1408] @ w2h([k][n]) -> g_y --------------
// CTA: 128 M x 256 N; 8 warps (2m x 4n), warp tile 64x64.
__global__ void __launch_bounds__(256) gemm2_kernel()
{
    int e = blockIdx.z;
    int cnt = g_cnt[e];
    int m0 = blockIdx.y * 128;
    if (m0 >= cnt) return;
    int base = g_base[e];
    int n0 = blockIdx.x * 256;

    extern __shared__ char smem[];
    uint32_t sb = smem_u32(smem);
    int tid = threadIdx.x, lane = tid & 31, wid = tid >> 5;
    int wm = wid >> 2, wn = wid & 3;

    uint32_t adst[4]; const __half* asrc[4];
#pragma unroll
    for (int i = 0; i < 4; i++) {
        int idx = tid + (i << 8);
        int r = idx >> 3, c = idx & 7;
        adst[i] = (uint32_t)(r * 128 + ((c ^ (r & 7)) << 4));
        asrc[i] = g_acth + (size_t)(base + m0 + r) * FFN_DIM + c * 8;
    }
    uint32_t bdst[8]; const __half* bsrc[8];
    const __half* w2e = g_w2h + (size_t)e * ((size_t)FFN_DIM * H_DIM);
#pragma unroll
    for (int i = 0; i < 8; i++) {
        int idx = tid + (i << 8);
        int r = idx >> 5, c = idx & 31;
        bdst[i] = (uint32_t)(r * 512 + ((((c & 24) | ((c ^ r) & 7))) << 4));
        bsrc[i] = w2e + (size_t)r * H_DIM + n0 + c * 8;
    }

    auto load_stage = [&](int t) {
        uint32_t ab = sb + (uint32_t)(t & 3) * STAGE_BYTES;
        uint32_t bb = ab + 16384u;
        int k0 = t * 64;
#pragma unroll
        for (int i = 0; i < 4; i++) cpa16(ab + adst[i], asrc[i] + k0);
#pragma unroll
        for (int i = 0; i < 8; i++) cpa16(bb + bdst[i], bsrc[i] + (size_t)k0 * H_DIM);
    };

    uint32_t aoffr = (uint32_t)((wm * 64 + (lane & 15)) * 128);
    uint32_t cxb = (uint32_t)(lane >> 4), rx = (uint32_t)(lane & 7);
    uint32_t klocal = ((lane >> 3) & 1) * 8 + (lane & 7);
    uint32_t bbase[4];
#pragma unroll
    for (int p = 0; p < 4; p++) {
        uint32_t unit = (uint32_t)(wn * 8 + p * 2) + (uint32_t)(lane >> 4);
        uint32_t usw = (unit & 24) | ((unit ^ (lane & 7)) & 7);
        bbase[p] = klocal * 512 + (usw << 4);
    }

    float acc[4][8][4] = {};

    load_stage(0); CPCOMMIT();
    load_stage(1); CPCOMMIT();
    load_stage(2); CPCOMMIT();

    const int NS = FFN_DIM / 64;  // 22
    for (int s = 0; s < NS; s++) {
        CPWAIT2();
        __syncthreads();
        if (s + 3 < NS) load_stage(s + 3);
        CPCOMMIT();
        uint32_t ab = sb + (uint32_t)(s & 3) * STAGE_BYTES;
        uint32_t bb = ab + 16384u;
#pragma unroll
        for (int kk = 0; kk < 4; kk++) {
            uint32_t cx = ((((uint32_t)kk << 1) + cxb) ^ rx) << 4;
            uint32_t af[4][4], bf[4][4];
#pragma unroll
            for (int mt = 0; mt < 4; mt++) ldm4(af[mt], ab + aoffr + mt * 2048 + cx);
#pragma unroll
            for (int p = 0; p < 4; p++) ldm4t(bf[p], bb + bbase[p] + (uint32_t)kk * 8192);
#pragma unroll
            for (int mt = 0; mt < 4; mt++)
#pragma unroll
                for (int p = 0; p < 4; p++) {
                    mma16(acc[mt][2 * p],     af[mt], bf[p][0], bf[p][1]);
                    mma16(acc[mt][2 * p + 1], af[mt], bf[p][2], bf[p][3]);
                }
        }
    }

    int gid = lane >> 2, tig = lane & 3;
#pragma unroll
    for (int mt = 0; mt < 4; mt++) {
        int r1 = m0 + wm * 64 + mt * 16 + gid;
#pragma unroll
        for (int j = 0; j < 8; j++) {
            int col = n0 + wn * 64 + j * 8 + tig * 2;
            if (r1 < cnt) {
                float2 o = make_float2(acc[mt][j][0], acc[mt][j][1]);
                *(float2*)&g_y[(size_t)(base + r1) * H_DIM + col] = o;
            }
            if (r1 + 8 < cnt) {
                float2 o = make_float2(acc[mt][j][2], acc[mt][j][3]);
                *(float2*)&g_y[(size_t)(base + r1 + 8) * H_DIM + col] = o;
            }
        }
    }
}

// ---------------- combine: out[t] = w0*Y[slot0] + w1*Y[slot1] --------------
__global__ void __launch_bounds__(256) combine_kernel(float* __restrict__ out)
{
    int t = blockIdx.x;
    int s0 = g_slot[2 * t], s1 = g_slot[2 * t + 1];
    float w0 = g_topk_w[2 * t], w1 = g_topk_w[2 * t + 1];
    const float* y0 = g_y + (size_t)s0 * H_DIM;
    const float* y1 = g_y + (size_t)s1 * H_DIM;
    float* orow = out + (size_t)t * H_DIM;

    int h = threadIdx.x * 4;
    float4 a = *(const float4*)(y0 + h);
    float4 b = *(const float4*)(y1 + h);
    float4 o;
    o.x = w0 * a.x + w1 * b.x;
    o.y = w0 * a.y + w1 * b.y;
    o.z = w0 * a.z + w1 * b.z;
    o.w = w0 * a.w + w1 * b.w;
    *(float4*)(orow + h) = o;
}

// ---------------- launch ----------------------------------------------------
extern "C" void kernel_launch(void* const* d_in, const int* in_sizes, int n_in,
                              void* d_out, int out_size)
{
    const float* hidden = (const float*)d_in[0];   // [S, B, H] == [T, H]
    const float* gate_w = (const float*)d_in[1];   // [E, H]
    const float* w1     = (const float*)d_in[2];   // [E, H, 2*FFN]
    const float* w2     = (const float*)d_in[3];   // [E, FFN, H]
    float* out          = (float*)d_out;

    static cudaStream_t s2 = nullptr;
    static cudaEvent_t ev_fork = nullptr, ev_join = nullptr;
    static bool attr_done = false;
    if (!s2) {
        cudaStreamCreateWithFlags(&s2, cudaStreamNonBlocking);
        cudaEventCreateWithFlags(&ev_fork, cudaEventDisableTiming);
        cudaEventCreateWithFlags(&ev_join, cudaEventDisableTiming);
    }
    if (!attr_done) {
        cudaFuncSetAttribute(gemm1_kernel, cudaFuncAttributeMaxDynamicSharedMemorySize, SMEM_BYTES);
        cudaFuncSetAttribute(gemm2_kernel, cudaFuncAttributeMaxDynamicSharedMemorySize, SMEM_BYTES);
        attr_done = true;
    }

    // Fork: weight conversion runs concurrently with gate/scatter.
    cudaEventRecord(ev_fork, 0);
    cudaStreamWaitEvent(s2, ev_fork, 0);
    convW_kernel<<<4096, 256, 0, s2>>>(w1, w2);
    cudaEventRecord(ev_join, s2);

    gate_kernel<<<T_DIM, 256>>>(hidden, gate_w);   // also writes g_xh (half)
    scatter_kernel<<<1, 256>>>();

    // Join: GEMMs need both branches.
    cudaStreamWaitEvent(0, ev_join, 0);
    gemm1_kernel<<<dim3(FFN_DIM / 128, NPAIR / 128, E_DIM), 256, SMEM_BYTES>>>();
    gemm2_kernel<<<dim3(H_DIM / 256, NPAIR / 128, E_DIM), 256, SMEM_BYTES>>>();
    combine_kernel<<<T_DIM, 256>>>(out);
}

// round 12
// speedup vs baseline: 1.1260x; 1.0902x over previous
#include <cuda_runtime.h>
#include <cuda_fp16.h>
#include <cstdint>

// Problem shapes (fixed by the dataset)
#define T_DIM 2048
#define H_DIM 1024
#define E_DIM 8
#define FFN_DIM 1408
#define FFN2_DIM 2816
#define NPAIR 4096
#define NPAD (NPAIR + 128)

// ---------------- scratch (device globals) ----------------------------------
__device__ int   g_topk_idx[T_DIM * 2];
__device__ float g_topk_w[T_DIM * 2];
__device__ int   g_tok[NPAIR];
__device__ int   g_slot[T_DIM * 2];
__device__ int   g_base[E_DIM];
__device__ int   g_cnt[E_DIM];
__device__ __align__(16) __half g_xh[(size_t)T_DIM * H_DIM];               // token rows (half)
__device__ __align__(16) __half g_acth[(size_t)NPAD * FFN_DIM];
__device__ __align__(16) float  g_y[(size_t)NPAIR * H_DIM];
__device__ __align__(16) __half g_w1h[(size_t)E_DIM * H_DIM * FFN2_DIM];   // native [k][n]
__device__ __align__(16) __half g_w2h[(size_t)E_DIM * FFN_DIM * H_DIM];    // native [k][n]

// ---------------- helpers ----------------------------------------------------
__device__ __forceinline__ uint32_t smem_u32(const void* p) {
    uint32_t a;
    asm("{ .reg .u64 t; cvta.to.shared.u64 t, %1; cvt.u32.u64 %0, t; }"
        : "=r"(a) : "l"(p));
    return a;
}
__device__ __forceinline__ void cpa16(uint32_t dst, const void* src) {
    asm volatile("cp.async.cg.shared.global [%0], [%1], 16;" :: "r"(dst), "l"(src));
}
#define CPCOMMIT() asm volatile("cp.async.commit_group;" ::: "memory")
#define CPWAIT2()  asm volatile("cp.async.wait_group 2;" ::: "memory")

__device__ __forceinline__ void ldm4(uint32_t* f, uint32_t a) {
    asm volatile("ldmatrix.sync.aligned.m8n8.x4.shared.b16 {%0,%1,%2,%3}, [%4];"
                 : "=r"(f[0]), "=r"(f[1]), "=r"(f[2]), "=r"(f[3]) : "r"(a));
}
__device__ __forceinline__ void ldm4t(uint32_t* f, uint32_t a) {
    asm volatile("ldmatrix.sync.aligned.m8n8.x4.trans.shared.b16 {%0,%1,%2,%3}, [%4];"
                 : "=r"(f[0]), "=r"(f[1]), "=r"(f[2]), "=r"(f[3]) : "r"(a));
}
__device__ __forceinline__ void mma16(float* c, const uint32_t* a,
                                      uint32_t b0, uint32_t b1) {
    asm volatile(
        "mma.sync.aligned.m16n8k16.row.col.f32.f16.f16.f32 "
        "{%0,%1,%2,%3}, {%4,%5,%6,%7}, {%8,%9}, {%0,%1,%2,%3};"
        : "+f"(c[0]), "+f"(c[1]), "+f"(c[2]), "+f"(c[3])
        : "r"(a[0]), "r"(a[1]), "r"(a[2]), "r"(a[3]), "r"(b0), "r"(b1));
}

// stage: A [128 m][64 k] half = 16KB at +0 ; B [64 k][256 n] half = 32KB at +16384
#define STAGE_BYTES 49152u
#define NSTAGE 4
#define SMEM_BYTES (NSTAGE * STAGE_BYTES)   // 196608
#define GTHREADS 512

// ---------------- gate: softmax top-2 + half conversion of the token row ----
__global__ void __launch_bounds__(256) gate_kernel(
    const float* __restrict__ x, const float* __restrict__ gw)
{
    int t = blockIdx.x;
    const float* xr = x + (size_t)t * H_DIM;
    int wid = threadIdx.x >> 5, lane = threadIdx.x & 31;
    __shared__ float sc[E_DIM];

    {
        float4 v = ((const float4*)xr)[threadIdx.x];
        __half2* d = (__half2*)(g_xh + (size_t)t * H_DIM);
        d[threadIdx.x * 2]     = __floats2half2_rn(v.x, v.y);
        d[threadIdx.x * 2 + 1] = __floats2half2_rn(v.z, v.w);
    }

    const float* g = gw + (size_t)wid * H_DIM;
    float s = 0.f;
    for (int i = lane; i < H_DIM; i += 32) s += xr[i] * g[i];
#pragma unroll
    for (int o = 16; o; o >>= 1) s += __shfl_xor_sync(0xffffffffu, s, o);
    if (lane == 0) sc[wid] = s;
    __syncthreads();

    if (threadIdx.x == 0) {
        float m = -1e30f;
#pragma unroll
        for (int e = 0; e < E_DIM; e++) m = fmaxf(m, sc[e]);
        float p[E_DIM], den = 0.f;
#pragma unroll
        for (int e = 0; e < E_DIM; e++) { p[e] = __expf(sc[e] - m); den += p[e]; }
        int i0 = 0;
#pragma unroll
        for (int e = 1; e < E_DIM; e++) if (p[e] > p[i0]) i0 = e;
        int i1 = -1;
#pragma unroll
        for (int e = 0; e < E_DIM; e++)
            if (e != i0 && (i1 < 0 || p[e] > p[i1])) i1 = e;
        float q0 = p[i0] / den, q1 = p[i1] / den;
        float wsum = q0 + q1 + 1e-20f;
        g_topk_idx[2 * t]     = i0;
        g_topk_idx[2 * t + 1] = i1;
        g_topk_w[2 * t]       = q0 / wsum;
        g_topk_w[2 * t + 1]   = q1 / wsum;
    }
}

// ---------------- scatter: deterministic compaction by expert --------------
__global__ void __launch_bounds__(256) scatter_kernel()
{
    int wid = threadIdx.x >> 5, lane = threadIdx.x & 31;
    __shared__ int scnt[E_DIM];

    int c = 0;
    for (int baset = 0; baset < T_DIM; baset += 32) {
        int t = baset + lane;
        bool m = (g_topk_idx[2 * t] == wid) || (g_topk_idx[2 * t + 1] == wid);
        unsigned b = __ballot_sync(0xffffffffu, m);
        c += __popc(b);
    }
    if (lane == 0) scnt[wid] = c;
    __syncthreads();
    if (threadIdx.x == 0) {
        int acc = 0;
        for (int e = 0; e < E_DIM; e++) { g_base[e] = acc; g_cnt[e] = scnt[e]; acc += scnt[e]; }
    }
    __syncthreads();

    int pos = g_base[wid];
    for (int baset = 0; baset < T_DIM; baset += 32) {
        int t = baset + lane;
        int k = -1;
        if (g_topk_idx[2 * t] == wid) k = 0;
        else if (g_topk_idx[2 * t + 1] == wid) k = 1;
        unsigned b = __ballot_sync(0xffffffffu, k >= 0);
        int off = __popc(b & ((1u << lane) - 1u));
        if (k >= 0) {
            g_tok[pos + off] = t;
            g_slot[2 * t + k] = pos + off;
        }
        pos += __popc(b);
    }
}

// ---------------- streaming f32 -> f16 cast for BOTH weights ----------------
__global__ void __launch_bounds__(256) convW_kernel(
    const float* __restrict__ w1, const float* __restrict__ w2)
{
    const size_t n1 = (size_t)E_DIM * H_DIM * FFN2_DIM / 4;
    const size_t n2 = (size_t)E_DIM * FFN_DIM * H_DIM / 4;
    size_t i = (size_t)blockIdx.x * blockDim.x + threadIdx.x;
    size_t stride = (size_t)gridDim.x * blockDim.x;
    for (; i < n1 + n2; i += stride) {
        const float4* s;
        uint2* d;
        size_t k;
        if (i < n1) { s = (const float4*)w1; d = (uint2*)g_w1h; k = i; }
        else        { s = (const float4*)w2; d = (uint2*)g_w2h; k = i - n1; }
        float4 v = s[k];
        __half2 h0 = __floats2half2_rn(v.x, v.y);
        __half2 h1 = __floats2half2_rn(v.z, v.w);
        d[k] = make_uint2(*(uint32_t*)&h0, *(uint32_t*)&h1);
    }
}

// ---------------- GEMM1: x_tok rows @ w1h([k][n]) -> swiglu -> g_acth -------
// CTA: 128 M x 128 FFN cols; 512 threads, 16 warps (4m x 4n), warp 32 x 64.
__global__ void __launch_bounds__(GTHREADS) gemm1_kernel()
{
    int e = blockIdx.z;
    int cnt = g_cnt[e];
    int m0 = blockIdx.y * 128;
    if (m0 >= cnt) return;
    int base = g_base[e];
    int n0 = blockIdx.x * 128;

    extern __shared__ char smem[];
    uint32_t sb = smem_u32(smem);
    int tid = threadIdx.x, lane = tid & 31, wid = tid >> 5;
    int wm = wid >> 2, wn = wid & 3;     // 4 x 4 warps

    uint32_t adst[2]; const __half* asrc[2];
#pragma unroll
    for (int i = 0; i < 2; i++) {
        int idx = tid + (i << 9);
        int r = idx >> 3, c = idx & 7;
        adst[i] = (uint32_t)(r * 128 + ((c ^ (r & 7)) << 4));
        int pr = base + m0 + r;
        if (pr > NPAIR - 1) pr = NPAIR - 1;
        int tok = g_tok[pr];
        asrc[i] = g_xh + (size_t)tok * H_DIM + c * 8;
    }
    uint32_t bdst[4]; const __half* bsrc[4];
    const __half* w1e = g_w1h + (size_t)e * ((size_t)H_DIM * FFN2_DIM);
#pragma unroll
    for (int i = 0; i < 4; i++) {
        int idx = tid + (i << 9);
        int r = idx >> 5, c = idx & 31;
        bdst[i] = (uint32_t)(r * 512 + ((((c & 24) | ((c ^ r) & 7))) << 4));
        int col = (c < 16) ? (n0 + c * 8) : (FFN_DIM + n0 + (c - 16) * 8);
        bsrc[i] = w1e + (size_t)r * FFN2_DIM + col;
    }

    auto load_stage = [&](int t) {
        uint32_t ab = sb + (uint32_t)(t & 3) * STAGE_BYTES;
        uint32_t bb = ab + 16384u;
        int k0 = t * 64;
#pragma unroll
        for (int i = 0; i < 2; i++) cpa16(ab + adst[i], asrc[i] + k0);
#pragma unroll
        for (int i = 0; i < 4; i++) cpa16(bb + bdst[i], bsrc[i] + (size_t)k0 * FFN2_DIM);
    };

    uint32_t aoffr = (uint32_t)((wm * 32 + (lane & 15)) * 128);
    uint32_t cxb = (uint32_t)(lane >> 4), rx = (uint32_t)(lane & 7);
    uint32_t klocal = ((lane >> 3) & 1) * 8 + (lane & 7);
    uint32_t bbase[4];
#pragma unroll
    for (int p = 0; p < 4; p++) {
        uint32_t u = (p < 2) ? (uint32_t)(wn * 4 + p * 2)
                             : (uint32_t)(16 + wn * 4 + (p - 2) * 2);
        uint32_t unit = u + (uint32_t)(lane >> 4);
        uint32_t usw = (unit & 24) | ((unit ^ (lane & 7)) & 7);
        bbase[p] = klocal * 512 + (usw << 4);
    }

    float acc[2][8][4] = {};

    load_stage(0); CPCOMMIT();
    load_stage(1); CPCOMMIT();
    load_stage(2); CPCOMMIT();

    const int NS = H_DIM / 64;  // 16
    for (int s = 0; s < NS; s++) {
        CPWAIT2();
        __syncthreads();
        if (s + 3 < NS) load_stage(s + 3);
        CPCOMMIT();
        uint32_t ab = sb + (uint32_t)(s & 3) * STAGE_BYTES;
        uint32_t bb = ab + 16384u;
#pragma unroll
        for (int kk = 0; kk < 4; kk++) {
            uint32_t cx = ((((uint32_t)kk << 1) + cxb) ^ rx) << 4;
            uint32_t af[2][4], bf[4][4];
#pragma unroll
            for (int mt = 0; mt < 2; mt++) ldm4(af[mt], ab + aoffr + mt * 2048 + cx);
#pragma unroll
            for (int p = 0; p < 4; p++) ldm4t(bf[p], bb + bbase[p] + (uint32_t)kk * 8192);
#pragma unroll
            for (int mt = 0; mt < 2; mt++)
#pragma unroll
                for (int p = 0; p < 4; p++) {
                    mma16(acc[mt][2 * p],     af[mt], bf[p][0], bf[p][1]);
                    mma16(acc[mt][2 * p + 1], af[mt], bf[p][2], bf[p][3]);
                }
        }
    }

    // epilogue: swiglu, store half
    int gid = lane >> 2, tig = lane & 3;
#pragma unroll
    for (int mt = 0; mt < 2; mt++) {
        int r1 = m0 + wm * 32 + mt * 16 + gid;
#pragma unroll
        for (int j = 0; j < 4; j++) {
            int col = n0 + wn * 32 + j * 8 + tig * 2;
            float g0 = acc[mt][j][0], g1 = acc[mt][j][1];
            float u0 = acc[mt][j + 4][0], u1 = acc[mt][j + 4][1];
            if (r1 < cnt) {
                __half2 h = __floats2half2_rn(g0 * u0 / (1.f + __expf(-g0)),
                                              g1 * u1 / (1.f + __expf(-g1)));
                *(__half2*)&g_acth[(size_t)(base + r1) * FFN_DIM + col] = h;
            }
            float g2 = acc[mt][j][2], g3 = acc[mt][j][3];
            float u2 = acc[mt][j + 4][2], u3 = acc[mt][j + 4][3];
            if (r1 + 8 < cnt) {
                __half2 h = __floats2half2_rn(g2 * u2 / (1.f + __expf(-g2)),
                                              g3 * u3 / (1.f + __expf(-g3)));
                *(__half2*)&g_acth[(size_t)(base + r1 + 8) * FFN_DIM + col] = h;
            }
        }
    }
}

// ---------------- GEMM2: g_acth[128,1408] @ w2h([k][n]) -> g_y --------------
// CTA: 128 M x 256 N; 512 threads, 16 warps (4m x 4n), warp 32 x 64.
__global__ void __launch_bounds__(GTHREADS) gemm2_kernel()
{
    int e = blockIdx.z;
    int cnt = g_cnt[e];
    int m0 = blockIdx.y * 128;
    if (m0 >= cnt) return;
    int base = g_base[e];
    int n0 = blockIdx.x * 256;

    extern __shared__ char smem[];
    uint32_t sb = smem_u32(smem);
    int tid = threadIdx.x, lane = tid & 31, wid = tid >> 5;
    int wm = wid >> 2, wn = wid & 3;

    uint32_t adst[2]; const __half* asrc[2];
#pragma unroll
    for (int i = 0; i < 2; i++) {
        int idx = tid + (i << 9);
        int r = idx >> 3, c = idx & 7;
        adst[i] = (uint32_t)(r * 128 + ((c ^ (r & 7)) << 4));
        asrc[i] = g_acth + (size_t)(base + m0 + r) * FFN_DIM + c * 8;
    }
    uint32_t bdst[4]; const __half* bsrc[4];
    const __half* w2e = g_w2h + (size_t)e * ((size_t)FFN_DIM * H_DIM);
#pragma unroll
    for (int i = 0; i < 4; i++) {
        int idx = tid + (i << 9);
        int r = idx >> 5, c = idx & 31;
        bdst[i] = (uint32_t)(r * 512 + ((((c & 24) | ((c ^ r) & 7))) << 4));
        bsrc[i] = w2e + (size_t)r * H_DIM + n0 + c * 8;
    }

    auto load_stage = [&](int t) {
        uint32_t ab = sb + (uint32_t)(t & 3) * STAGE_BYTES;
        uint32_t bb = ab + 16384u;
        int k0 = t * 64;
#pragma unroll
        for (int i = 0; i < 2; i++) cpa16(ab + adst[i], asrc[i] + k0);
#pragma unroll
        for (int i = 0; i < 4; i++) cpa16(bb + bdst[i], bsrc[i] + (size_t)k0 * H_DIM);
    };

    uint32_t aoffr = (uint32_t)((wm * 32 + (lane & 15)) * 128);
    uint32_t cxb = (uint32_t)(lane >> 4), rx = (uint32_t)(lane & 7);
    uint32_t klocal = ((lane >> 3) & 1) * 8 + (lane & 7);
    uint32_t bbase[4];
#pragma unroll
    for (int p = 0; p < 4; p++) {
        uint32_t unit = (uint32_t)(wn * 8 + p * 2) + (uint32_t)(lane >> 4);
        uint32_t usw = (unit & 24) | ((unit ^ (lane & 7)) & 7);
        bbase[p] = klocal * 512 + (usw << 4);
    }

    float acc[2][8][4] = {};

    load_stage(0); CPCOMMIT();
    load_stage(1); CPCOMMIT();
    load_stage(2); CPCOMMIT();

    const int NS = FFN_DIM / 64;  // 22
    for (int s = 0; s < NS; s++) {
        CPWAIT2();
        __syncthreads();
        if (s + 3 < NS) load_stage(s + 3);
        CPCOMMIT();
        uint32_t ab = sb + (uint32_t)(s & 3) * STAGE_BYTES;
        uint32_t bb = ab + 16384u;
#pragma unroll
        for (int kk = 0; kk < 4; kk++) {
            uint32_t cx = ((((uint32_t)kk << 1) + cxb) ^ rx) << 4;
            uint32_t af[2][4], bf[4][4];
#pragma unroll
            for (int mt = 0; mt < 2; mt++) ldm4(af[mt], ab + aoffr + mt * 2048 + cx);
#pragma unroll
            for (int p = 0; p < 4; p++) ldm4t(bf[p], bb + bbase[p] + (uint32_t)kk * 8192);
#pragma unroll
            for (int mt = 0; mt < 2; mt++)
#pragma unroll
                for (int p = 0; p < 4; p++) {
                    mma16(acc[mt][2 * p],     af[mt], bf[p][0], bf[p][1]);
                    mma16(acc[mt][2 * p + 1], af[mt], bf[p][2], bf[p][3]);
                }
        }
    }

    int gid = lane >> 2, tig = lane & 3;
#pragma unroll
    for (int mt = 0; mt < 2; mt++) {
        int r1 = m0 + wm * 32 + mt * 16 + gid;
#pragma unroll
        for (int j = 0; j < 8; j++) {
            int col = n0 + wn * 64 + j * 8 + tig * 2;
            if (r1 < cnt) {
                float2 o = make_float2(acc[mt][j][0], acc[mt][j][1]);
                *(float2*)&g_y[(size_t)(base + r1) * H_DIM + col] = o;
            }
            if (r1 + 8 < cnt) {
                float2 o = make_float2(acc[mt][j][2], acc[mt][j][3]);
                *(float2*)&g_y[(size_t)(base + r1 + 8) * H_DIM + col] = o;
            }
        }
    }
}

// ---------------- combine: out[t] = w0*Y[slot0] + w1*Y[slot1] --------------
__global__ void __launch_bounds__(256) combine_kernel(float* __restrict__ out)
{
    int t = blockIdx.x;
    int s0 = g_slot[2 * t], s1 = g_slot[2 * t + 1];
    float w0 = g_topk_w[2 * t], w1 = g_topk_w[2 * t + 1];
    const float* y0 = g_y + (size_t)s0 * H_DIM;
    const float* y1 = g_y + (size_t)s1 * H_DIM;
    float* orow = out + (size_t)t * H_DIM;

    int h = threadIdx.x * 4;
    float4 a = *(const float4*)(y0 + h);
    float4 b = *(const float4*)(y1 + h);
    float4 o;
    o.x = w0 * a.x + w1 * b.x;
    o.y = w0 * a.y + w1 * b.y;
    o.z = w0 * a.z + w1 * b.z;
    o.w = w0 * a.w + w1 * b.w;
    *(float4*)(orow + h) = o;
}

// ---------------- launch ----------------------------------------------------
extern "C" void kernel_launch(void* const* d_in, const int* in_sizes, int n_in,
                              void* d_out, int out_size)
{
    const float* hidden = (const float*)d_in[0];   // [S, B, H] == [T, H]
    const float* gate_w = (const float*)d_in[1];   // [E, H]
    const float* w1     = (const float*)d_in[2];   // [E, H, 2*FFN]
    const float* w2     = (const float*)d_in[3];   // [E, FFN, H]
    float* out          = (float*)d_out;

    static cudaStream_t s2 = nullptr;
    static cudaEvent_t ev_fork = nullptr, ev_join = nullptr;
    static bool attr_done = false;
    if (!s2) {
        cudaStreamCreateWithFlags(&s2, cudaStreamNonBlocking);
        cudaEventCreateWithFlags(&ev_fork, cudaEventDisableTiming);
        cudaEventCreateWithFlags(&ev_join, cudaEventDisableTiming);
    }
    if (!attr_done) {
        cudaFuncSetAttribute(gemm1_kernel, cudaFuncAttributeMaxDynamicSharedMemorySize, SMEM_BYTES);
        cudaFuncSetAttribute(gemm2_kernel, cudaFuncAttributeMaxDynamicSharedMemorySize, SMEM_BYTES);
        attr_done = true;
    }

    // Fork: weight conversion runs concurrently with gate/scatter.
    cudaEventRecord(ev_fork, 0);
    cudaStreamWaitEvent(s2, ev_fork, 0);
    convW_kernel<<<4096, 256, 0, s2>>>(w1, w2);
    cudaEventRecord(ev_join, s2);

    gate_kernel<<<T_DIM, 256>>>(hidden, gate_w);   // also writes g_xh (half)
    scatter_kernel<<<1, 256>>>();

    // Join: GEMMs need both branches.
    cudaStreamWaitEvent(0, ev_join, 0);
    gemm1_kernel<<<dim3(FFN_DIM / 128, NPAIR / 128, E_DIM), GTHREADS, SMEM_BYTES>>>();
    gemm2_kernel<<<dim3(H_DIM / 256, NPAIR / 128, E_DIM), GTHREADS, SMEM_BYTES>>>();
    combine_kernel<<<T_DIM, 256>>>(out);
}